// round 16
// baseline (speedup 1.0000x reference)
#include <cuda_runtime.h>
#include <cuda_fp16.h>

// Single fused persistent kernel: phase 1 converts h to fp16 (g_hh), software
// grid barrier (all 888 blocks co-resident: 6/SM x 148 SM, regs<=42, smem 0),
// phase 2 gathers. Balanced contiguous chunk partition removes the strided
// sweep's partial-tail idle and makes per-warp index loads sequential.
// Barrier phase uses a monotonically increasing generation word snapshotted at
// entry (count resets each call; identical work/output every call).

#define MAX_HELEM 12800000   // 100000 nodes * 128 feat

__device__ __half g_hh[MAX_HELEM];
__device__ unsigned g_cnt;   // zero-init
__device__ unsigned g_gen;   // zero-init, monotonic across calls

// 16-element dot (two uint4 per operand = 8 half2):
// 8 HMUL2 -> 16 products, 4 HADD2 (pairwise), 4 converts, fp32 tail.
__device__ __forceinline__ float dot16h(uint4 u0, uint4 u1, uint4 v0, uint4 v1)
{
    const __half2* a  = reinterpret_cast<const __half2*>(&u0);
    const __half2* a2 = reinterpret_cast<const __half2*>(&u1);
    const __half2* b  = reinterpret_cast<const __half2*>(&v0);
    const __half2* b2 = reinterpret_cast<const __half2*>(&v1);

    __half2 p0 = __hmul2(a[0], b[0]);
    __half2 p1 = __hmul2(a[1], b[1]);
    __half2 p2 = __hmul2(a[2], b[2]);
    __half2 p3 = __hmul2(a[3], b[3]);
    __half2 p4 = __hmul2(a2[0], b2[0]);
    __half2 p5 = __hmul2(a2[1], b2[1]);
    __half2 p6 = __hmul2(a2[2], b2[2]);
    __half2 p7 = __hmul2(a2[3], b2[3]);

    __half2 q0 = __hadd2(p0, p1);
    __half2 q1 = __hadd2(p2, p3);
    __half2 q2 = __hadd2(p4, p5);
    __half2 q3 = __hadd2(p6, p7);

    float2 f0 = __half22float2(q0);
    float2 f1 = __half22float2(q1);
    float2 f2 = __half22float2(q2);
    float2 f3 = __half22float2(q3);

    return (f0.x + f0.y) + (f1.x + f1.y) + ((f2.x + f2.y) + (f3.x + f3.y));
}

__global__ void __launch_bounds__(256, 6) fused_edge_dot(
    const float* __restrict__ h,
    const int* __restrict__ src,
    const int* __restrict__ dst,
    float* __restrict__ out,
    int n8,            // n_elem / 8
    int n_edges)
{
    const unsigned start_gen = *(volatile unsigned*)&g_gen;

    // ---- phase 1: fp32 -> fp16 convert (grid-stride, 8 floats/thread/iter)
    {
        int i = blockIdx.x * blockDim.x + threadIdx.x;
        int stride = gridDim.x * blockDim.x;
        uint4* __restrict__ outp = reinterpret_cast<uint4*>(g_hh);
        const float4* __restrict__ inp = reinterpret_cast<const float4*>(h);
        for (; i < n8; i += stride) {
            float4 v0 = __ldg(inp + 2 * i);
            float4 v1 = __ldg(inp + 2 * i + 1);
            __half2 p0 = __floats2half2_rn(v0.x, v0.y);
            __half2 p1 = __floats2half2_rn(v0.z, v0.w);
            __half2 p2 = __floats2half2_rn(v1.x, v1.y);
            __half2 p3 = __floats2half2_rn(v1.z, v1.w);
            uint4 u;
            u.x = *reinterpret_cast<unsigned*>(&p0);
            u.y = *reinterpret_cast<unsigned*>(&p1);
            u.z = *reinterpret_cast<unsigned*>(&p2);
            u.w = *reinterpret_cast<unsigned*>(&p3);
            outp[i] = u;
        }
    }

    // ---- barrier arrive (release our stores first)
    __threadfence();
    __syncthreads();
    if (threadIdx.x == 0) {
        unsigned a = atomicAdd(&g_cnt, 1);
        if (a == gridDim.x - 1) {
            g_cnt = 0;
            __threadfence();
            atomicAdd(&g_gen, 1);     // release all spinners
        }
    }

    // ---- overlap window: partition + first-chunk index prefetch
    const int wib  = threadIdx.x >> 5;
    const int lane = threadIdx.x & 31;
    const int g = lane >> 3;
    const int t = lane & 7;
    const unsigned FULL = 0xFFFFFFFFu;

    const int C  = (n_edges + 7) >> 3;           // total chunks of 8 edges
    const int NW = gridDim.x * 8;                // total warps
    const int W  = blockIdx.x * 8 + wib;
    const int q  = C / NW;
    const int r  = C - q * NW;
    const int cnt = q + (W < r);
    const int s0  = q * W + (W < r ? W : r);     // first chunk (contiguous run)

    const int2* __restrict__ src2 = reinterpret_cast<const int2*>(src);
    const int2* __restrict__ dst2 = reinterpret_cast<const int2*>(dst);

    int e0 = s0 * 8;
    int2 si = make_int2(0, 0), di = make_int2(0, 0);
    if (cnt > 0 && e0 + 7 < n_edges) {
        si = __ldg(src2 + (e0 >> 1) + g);
        di = __ldg(dst2 + (e0 >> 1) + g);
    }

    // ---- barrier wait
    if (threadIdx.x == 0) {
        while (*(volatile unsigned*)&g_gen == start_gen) __nanosleep(64);
    }
    __syncthreads();
    __threadfence();
    if (cnt == 0) return;

    const uint4* __restrict__ hb = reinterpret_cast<const uint4*>(g_hh);

    // ---- phase 2: gather over contiguous chunks
    for (int i = 0; i < cnt; i++) {
        // prefetch next chunk's indices (contiguous -> mostly L1 hits)
        int2 si2 = make_int2(0, 0), di2 = make_int2(0, 0);
        int e0n = e0 + 8;
        if (i + 1 < cnt && e0n + 7 < n_edges) {
            si2 = __ldg(src2 + (e0n >> 1) + g);
            di2 = __ldg(dst2 + (e0n >> 1) + g);
        }

        const uint4* psA = hb + (size_t)si.x * 16 + t;
        const uint4* pdA = hb + (size_t)di.x * 16 + t;
        const uint4* psB = hb + (size_t)si.y * 16 + t;
        const uint4* pdB = hb + (size_t)di.y * 16 + t;

        uint4 a0 = __ldg(psA);  uint4 a1 = __ldg(psA + 8);
        uint4 b0 = __ldg(pdA);  uint4 b1 = __ldg(pdA + 8);
        uint4 c0 = __ldg(psB);  uint4 c1 = __ldg(psB + 8);
        uint4 f0 = __ldg(pdB);  uint4 f1 = __ldg(pdB + 8);

        float accA = dot16h(a0, a1, b0, b1);
        float accB = dot16h(c0, c1, f0, f1);

        accA += __shfl_xor_sync(FULL, accA, 4);
        accB += __shfl_xor_sync(FULL, accB, 4);
        accA += __shfl_xor_sync(FULL, accA, 2);
        accB += __shfl_xor_sync(FULL, accB, 2);
        accA += __shfl_xor_sync(FULL, accA, 1);
        accB += __shfl_xor_sync(FULL, accB, 1);

        if (t == 0) {
            int ea = e0 + 2 * g;
            if (ea + 1 < n_edges) {
                *reinterpret_cast<float2*>(out + ea) = make_float2(accA, accB);
            } else if (ea < n_edges) {
                out[ea] = accA;
            }
        }

        e0 = e0n;
        si = si2;
        di = di2;
    }
}

extern "C" void kernel_launch(void* const* d_in, const int* in_sizes, int n_in,
                              void* d_out, int out_size)
{
    const float* h   = (const float*)d_in[0];
    const int*   src = (const int*)d_in[1];
    const int*   dst = (const int*)d_in[2];
    float* out = (float*)d_out;

    int n_elem  = in_sizes[0];               // nodes * 128
    int n_edges = in_sizes[1];               // E = 640000

    // grid MUST equal full residency (6 blocks/SM x 148 SMs) so the software
    // barrier is deadlock-free: every block is co-resident.
    fused_edge_dot<<<888, 256>>>(h, src, dst, out, n_elem / 8, n_edges);
}

// round 17
// speedup vs baseline: 1.0773x; 1.0773x over previous
#include <cuda_runtime.h>
#include <cuda_fp16.h>

// Two kernels + PDL (proven best structure, R15) with R16's balanced
// CONTIGUOUS chunk partition in the gather kernel: each warp owns 11-12
// consecutive 8-edge chunks (no strided-sweep partial tail; sequential
// per-warp index loads -> mostly L1 hits on the prefetch).
// fp16 gather table (halves L1TEX wavefronts), half2 dot math, 48 warps/SM.

#define MAX_HELEM 12800000   // 100000 nodes * 128 feat

__device__ __half g_hh[MAX_HELEM];

// fp32 -> fp16: 8 floats per iter (2x float4 in, 1x uint4 out).
__global__ void __launch_bounds__(256) k_convert(const float* __restrict__ h, int n8)
{
    cudaTriggerProgrammaticLaunchCompletion();

    int i = blockIdx.x * blockDim.x + threadIdx.x;
    int stride = gridDim.x * blockDim.x;
    uint4* __restrict__ outp = reinterpret_cast<uint4*>(g_hh);
    const float4* __restrict__ inp = reinterpret_cast<const float4*>(h);
    for (; i < n8; i += stride) {
        float4 v0 = __ldg(inp + 2 * i);
        float4 v1 = __ldg(inp + 2 * i + 1);
        __half2 p0 = __floats2half2_rn(v0.x, v0.y);
        __half2 p1 = __floats2half2_rn(v0.z, v0.w);
        __half2 p2 = __floats2half2_rn(v1.x, v1.y);
        __half2 p3 = __floats2half2_rn(v1.z, v1.w);
        uint4 u;
        u.x = *reinterpret_cast<unsigned*>(&p0);
        u.y = *reinterpret_cast<unsigned*>(&p1);
        u.z = *reinterpret_cast<unsigned*>(&p2);
        u.w = *reinterpret_cast<unsigned*>(&p3);
        outp[i] = u;
    }
}

// 16-element dot (two uint4 per operand = 8 half2):
// 8 HMUL2 -> 16 products, 4 HADD2 (pairwise), 4 converts, fp32 tail.
__device__ __forceinline__ float dot16h(uint4 u0, uint4 u1, uint4 v0, uint4 v1)
{
    const __half2* a  = reinterpret_cast<const __half2*>(&u0);
    const __half2* a2 = reinterpret_cast<const __half2*>(&u1);
    const __half2* b  = reinterpret_cast<const __half2*>(&v0);
    const __half2* b2 = reinterpret_cast<const __half2*>(&v1);

    __half2 p0 = __hmul2(a[0], b[0]);
    __half2 p1 = __hmul2(a[1], b[1]);
    __half2 p2 = __hmul2(a[2], b[2]);
    __half2 p3 = __hmul2(a[3], b[3]);
    __half2 p4 = __hmul2(a2[0], b2[0]);
    __half2 p5 = __hmul2(a2[1], b2[1]);
    __half2 p6 = __hmul2(a2[2], b2[2]);
    __half2 p7 = __hmul2(a2[3], b2[3]);

    __half2 q0 = __hadd2(p0, p1);
    __half2 q1 = __hadd2(p2, p3);
    __half2 q2 = __hadd2(p4, p5);
    __half2 q3 = __hadd2(p6, p7);

    float2 f0 = __half22float2(q0);
    float2 f1 = __half22float2(q1);
    float2 f2 = __half22float2(q2);
    float2 f3 = __half22float2(q3);

    return (f0.x + f0.y) + (f1.x + f1.y) + ((f2.x + f2.y) + (f3.x + f3.y));
}

// Persistent gather kernel over fp16 rows (256B = 16 uint4 chunks).
// Warp owns a contiguous run of chunks; chunk = 8 edges; 8-lane group g
// handles edges e0+2g (A), e0+2g+1 (B). Per lane: 2 int2 index loads +
// 8 independent LDG.128 gathers, half2 dot, two 3-level butterflies,
// group leader stores float2.
__global__ void __launch_bounds__(256, 6) edge_dot_f16(
    const int* __restrict__ src,
    const int* __restrict__ dst,
    float* __restrict__ out,
    int n_edges)
{
    const int wib  = threadIdx.x >> 5;
    const int lane = threadIdx.x & 31;
    const int g = lane >> 3;
    const int t = lane & 7;
    const unsigned FULL = 0xFFFFFFFFu;

    // balanced contiguous partition of C chunks over NW warps
    const int C  = (n_edges + 7) >> 3;
    const int NW = gridDim.x * 8;
    const int W  = blockIdx.x * 8 + wib;
    const int q  = C / NW;
    const int r  = C - q * NW;
    const int cnt = q + (W < r);
    const int s0  = q * W + (W < r ? W : r);

    const int2* __restrict__ src2 = reinterpret_cast<const int2*>(src);
    const int2* __restrict__ dst2 = reinterpret_cast<const int2*>(dst);

    // table-independent prologue (overlaps k_convert under PDL)
    int e0 = s0 * 8;
    int2 si = make_int2(0, 0), di = make_int2(0, 0);
    if (cnt > 0) {
        si = __ldg(src2 + (e0 >> 1) + g);
        di = __ldg(dst2 + (e0 >> 1) + g);
    }

    cudaGridDependencySynchronize();
    if (cnt == 0) return;

    const uint4* __restrict__ hb = reinterpret_cast<const uint4*>(g_hh);

    for (int i = 0; i < cnt; i++) {
        // prefetch next chunk's indices (sequential -> mostly L1 hits)
        int2 si2 = make_int2(0, 0), di2 = make_int2(0, 0);
        int e0n = e0 + 8;
        if (i + 1 < cnt) {
            si2 = __ldg(src2 + (e0n >> 1) + g);
            di2 = __ldg(dst2 + (e0n >> 1) + g);
        }

        const uint4* psA = hb + (size_t)si.x * 16 + t;
        const uint4* pdA = hb + (size_t)di.x * 16 + t;
        const uint4* psB = hb + (size_t)si.y * 16 + t;
        const uint4* pdB = hb + (size_t)di.y * 16 + t;

        uint4 a0 = __ldg(psA);  uint4 a1 = __ldg(psA + 8);
        uint4 b0 = __ldg(pdA);  uint4 b1 = __ldg(pdA + 8);
        uint4 c0 = __ldg(psB);  uint4 c1 = __ldg(psB + 8);
        uint4 f0 = __ldg(pdB);  uint4 f1 = __ldg(pdB + 8);

        float accA = dot16h(a0, a1, b0, b1);
        float accB = dot16h(c0, c1, f0, f1);

        accA += __shfl_xor_sync(FULL, accA, 4);
        accB += __shfl_xor_sync(FULL, accB, 4);
        accA += __shfl_xor_sync(FULL, accA, 2);
        accB += __shfl_xor_sync(FULL, accB, 2);
        accA += __shfl_xor_sync(FULL, accA, 1);
        accB += __shfl_xor_sync(FULL, accB, 1);

        if (t == 0) {
            int ea = e0 + 2 * g;
            if (ea + 1 < n_edges) {
                *reinterpret_cast<float2*>(out + ea) = make_float2(accA, accB);
            } else if (ea < n_edges) {
                out[ea] = accA;
            }
        }

        e0 = e0n;
        si = si2;
        di = di2;
    }
}

extern "C" void kernel_launch(void* const* d_in, const int* in_sizes, int n_in,
                              void* d_out, int out_size)
{
    const float* h   = (const float*)d_in[0];
    const int*   src = (const int*)d_in[1];
    const int*   dst = (const int*)d_in[2];
    float* out = (float*)d_out;

    int n_elem  = in_sizes[0];               // nodes * 128
    int n_edges = in_sizes[1];               // E = 640000

    k_convert<<<888, 256>>>(h, n_elem / 8);

    // PDL launch: overlaps edge_dot's launch + index prologue with k_convert
    cudaLaunchConfig_t cfg = {};
    cfg.gridDim  = dim3(888, 1, 1);
    cfg.blockDim = dim3(256, 1, 1);
    cfg.dynamicSmemBytes = 0;
    cfg.stream = 0;
    cudaLaunchAttribute attrs[1];
    attrs[0].id = cudaLaunchAttributeProgrammaticStreamSerialization;
    attrs[0].val.programmaticStreamSerializationAllowed = 1;
    cfg.attrs = attrs;
    cfg.numAttrs = 1;
    cudaLaunchKernelEx(&cfg, edge_dot_f16, src, dst, out, n_edges);
}